// round 11
// baseline (speedup 1.0000x reference)
#include <cuda_runtime.h>
#include <cuda.h>
#include <cstdint>

// Problem constants (reference: D=48, K=12, S=4, BS=8)
#define D_   48
#define N_   (D_ * D_)      // 2304
#define K_   12
#define KK_  (K_ * K_)      // 144
#define NW1_ 10
#define NW_  (NW1_ * NW1_)  // 100
#define BS_  8

#define WIN_FLOATS (KK_ * KK_)            // 20736 floats per window
#define WIN_BYTES  (WIN_FLOATS * 4)       // 82944 B

// View x[b] as x4[pr][pc][qr][qc] (48^4):  x[b, pr*48+pc, qr*48+qc].
// out[b, w, (ia,ib), (ja,jb)] = x4[b][4wr+ia][4wc+ib][4wr+ja][4wc+jb].
// ONE 5D TMA box [qc=12, qr=12, pc=12, pr=12, b=1] at (4wc,4wr,4wc,4wr,b)
// packs the ENTIRE window densely into smem in [pr=ia][pc=ib][qr=ja][qc=jb]
// order == the exact contiguous 82944B output chunk for (b,w).
// Then one bulk store. Zero per-element SM work; 2 CTAs/SM overlap
// load & store phases.

__global__ void __launch_bounds__(32) subm_tma_window(
    const __grid_constant__ CUtensorMap tmap, float* __restrict__ out)
{
    extern __shared__ __align__(128) float T[];     // WIN_FLOATS
    __shared__ __align__(8) unsigned long long mbar;

    if (threadIdx.x != 0) return;

    int blk = blockIdx.x;          // = b*100 + w
    int w   = blk % NW_;
    int b   = blk / NW_;
    int wr  = w / NW1_;
    int wc  = w % NW1_;

    uint32_t s_tile, s_mbar;
    asm("{ .reg .u64 t; cvta.to.shared.u64 t, %1; cvt.u32.u64 %0, t; }"
        : "=r"(s_tile) : "l"(T));
    asm("{ .reg .u64 t; cvta.to.shared.u64 t, %1; cvt.u32.u64 %0, t; }"
        : "=r"(s_mbar) : "l"(&mbar));

    asm volatile("mbarrier.init.shared.b64 [%0], 1;" :: "r"(s_mbar) : "memory");
    asm volatile("fence.proxy.async.shared::cta;" ::: "memory");

    asm volatile("mbarrier.arrive.expect_tx.shared.b64 _, [%0], %1;"
                 :: "r"(s_mbar), "r"((uint32_t)WIN_BYTES) : "memory");
    asm volatile(
        "cp.async.bulk.tensor.5d.shared::cta.global.tile.mbarrier::complete_tx::bytes "
        "[%0], [%1, {%2, %3, %4, %5, %6}], [%7];"
        :: "r"(s_tile), "l"(&tmap),
           "r"(4 * wc), "r"(4 * wr), "r"(4 * wc), "r"(4 * wr), "r"(b),
           "r"(s_mbar)
        : "memory");

    // Wait for TMA completion (phase 0)
    asm volatile(
        "{\n\t"
        ".reg .pred P1;\n\t"
        "LW%=:\n\t"
        "mbarrier.try_wait.parity.shared.b64 P1, [%0], 0;\n\t"
        "@P1 bra LD%=;\n\t"
        "bra LW%=;\n\t"
        "LD%=:\n\t"
        "}"
        :: "r"(s_mbar) : "memory");

    float* dst = out + (size_t)blk * WIN_FLOATS;
    asm volatile(
        "cp.async.bulk.global.shared::cta.bulk_group [%0], [%1], %2;"
        :: "l"(dst), "r"(s_tile), "r"((uint32_t)WIN_BYTES) : "memory");
    asm volatile("cp.async.bulk.commit_group;" ::: "memory");
    asm volatile("cp.async.bulk.wait_group 0;" ::: "memory");
}

// ---------------- fallback (plain gather, best known LDG design) ----------
__global__ void __launch_bounds__(256) submanifold_gather_q12(
    const float* __restrict__ x, float* __restrict__ out)
{
    int t = blockIdx.x * 256 + threadIdx.x;
    int q    = t % 36;
    int rest = t / 36;
    int ia   = rest % K_;
    rest     = rest / K_;
    int w    = rest % NW_;
    int b    = rest / NW_;
    int wr = w / NW1_;
    int wc = w % NW1_;
    int ja  = q / 3;
    int sub = q % 3;
    int r0 = (wr * 4 + ia) * D_ + wc * 4;
    int c  = (wr * 4 + ja) * D_ + wc * 4 + sub * 4;
    const float4* src = reinterpret_cast<const float4*>(x + ((size_t)b * N_ + r0) * N_ + c);
    size_t dbase = (((size_t)(b * NW_ + w)) * KK_ + ia * K_) * 36 + q;
    float4* dst = reinterpret_cast<float4*>(out) + dbase;
#pragma unroll
    for (int ib = 0; ib < K_; ib++)
        dst[(size_t)ib * 36] = src[(size_t)ib * (N_ / 4)];
}

// ---------------------------------------------------------------------------

typedef CUresult (*PFN_tmapEncode)(
    CUtensorMap*, CUtensorMapDataType, cuuint32_t, void*,
    const cuuint64_t*, const cuuint64_t*, const cuuint32_t*, const cuuint32_t*,
    CUtensorMapInterleave, CUtensorMapSwizzle, CUtensorMapL2promotion,
    CUtensorMapFloatOOBfill);

extern "C" void kernel_launch(void* const* d_in, const int* in_sizes, int n_in,
                              void* d_out, int out_size)
{
    float* x   = (float*)d_in[0];
    float* out = (float*)d_out;

    PFN_tmapEncode encode = nullptr;
    cudaDriverEntryPointQueryResult qres;
    cudaGetDriverEntryPoint("cuTensorMapEncodeTiled", (void**)&encode,
                            cudaEnableDefault, &qres);

    bool tma_ok = false;
    CUtensorMap tmap;
    if (encode && qres == cudaDriverEntryPointSuccess) {
        // 5D view of x: dims (innermost->outermost) [qc, qr, pc, pr, b]
        cuuint64_t dims[5]    = {48, 48, 48, 48, (cuuint64_t)BS_};
        cuuint64_t strides[4] = {
            48ull * 4,                    // qr : 192 B
            (cuuint64_t)N_ * 4,           // pc : 9216 B
            48ull * N_ * 4,               // pr : 442368 B
            (cuuint64_t)N_ * N_ * 4       // b  : 21233664 B
        };
        cuuint32_t box[5]  = {12, 12, 12, 12, 1};
        cuuint32_t estr[5] = {1, 1, 1, 1, 1};
        CUresult r = encode(&tmap, CU_TENSOR_MAP_DATA_TYPE_FLOAT32, 5, (void*)x,
                            dims, strides, box, estr,
                            CU_TENSOR_MAP_INTERLEAVE_NONE,
                            CU_TENSOR_MAP_SWIZZLE_NONE,
                            CU_TENSOR_MAP_L2_PROMOTION_L2_128B,
                            CU_TENSOR_MAP_FLOAT_OOB_FILL_NONE);
        tma_ok = (r == CUDA_SUCCESS);
        if (tma_ok) {
            cudaError_t e = cudaFuncSetAttribute(
                subm_tma_window,
                cudaFuncAttributeMaxDynamicSharedMemorySize, WIN_BYTES);
            if (e != cudaSuccess) tma_ok = false;
        }
    }

    if (tma_ok) {
        subm_tma_window<<<BS_ * NW_, 32, WIN_BYTES>>>(tmap, out);  // 800 CTAs
    } else {
        const int total_threads = BS_ * NW_ * K_ * 36;
        submanifold_gather_q12<<<total_threads / 256, 256>>>(x, out);
    }
}